// round 9
// baseline (speedup 1.0000x reference)
#include <cuda_runtime.h>
#include <cstdint>

// BlockMaskGenerator: 4 random rectangles per batch -> 256 x 16384 bool
// target mask + complement context mask (bool promoted to f32 by harness).
//   d_out = [context_mask (256*16384 f32), target_mask (256*16384 f32)]
// R8 postmortem: L2-active time ~= LTS floor (5.2K cyc) but kernel is 15K cyc:
// per-element value ALU + store-issue exposure dominates. R9: split into
// (F) pure-constant coalesced fill (ctx=1, tgt=0) that rides the L2 cap, and
// (R) per-rect raster kernel overwriting only rectangle interiors (~13MB).

#define BM_BATCH   256
#define BM_NBLK    4
#define BM_H       128
#define BM_W       128
#define BM_SEQ     (BM_H * BM_W)
#define BM_HALF    (BM_BATCH * BM_SEQ)      // 4,194,304 floats per mask

// ---------- Kernel F: constant fill (ctx=1.0 / tgt=0.0) ----------
// 2048 CTAs x 256 thr; CTA covers 4096 contiguous floats (16KB).
// Warp store s covers one contiguous 512B row-chunk: fully coalesced.
__global__ __launch_bounds__(256, 8)
void fill_kernel(float* __restrict__ out)
{
    const int bid  = blockIdx.x;
    const int tid  = threadIdx.x;
    const int lane = tid & 31;
    const int warp = tid >> 5;

    const unsigned v = (bid < 1024) ? 0x3F800000u : 0u;   // ctx half : tgt half
    const uint4 q = make_uint4(v, v, v, v);

    float* base = out + (size_t)bid * 4096 + (size_t)warp * 512 + (size_t)lane * 4;
#pragma unroll
    for (int s = 0; s < 4; s++)
        *reinterpret_cast<uint4*>(base + (size_t)s * 128) = q;
}

// ---------- Kernel R: rasterize rectangle interiors ----------
// 1024 CTAs (one per rect) x 128 thr. Thread 0 computes the rect (exact
// IEEE-rn sequence matching JAX), 4 warps sweep rows, lanes sweep cols.
__global__ __launch_bounds__(128, 8)
void raster_kernel(const float* __restrict__ scales_u,
                   const float* __restrict__ rand_top,
                   const float* __restrict__ rand_left,
                   float* __restrict__ out)
{
    __shared__ int s_top, s_left, s_h, s_w;

    const int i   = blockIdx.x;          // rect index 0..1023
    const int b   = i >> 2;              // batch
    const int tid = threadIdx.x;

    if (tid == 0) {
        // scales = 0.15 + u*0.05 (separate mul/add, f32 rn — match JAX; no FMA)
        float scale = __fadd_rn(0.15f, __fmul_rn(scales_u[i], 0.05f));
        float areaf = __fmul_rn(__fmul_rn(scale, 128.0f), 128.0f); // pow2 exact
        int area = (int)areaf;                                     // trunc
        int h = (int)__fsqrt_rn(__fdiv_rn((float)area, 0.75f));
        h = min(max(h, 1), BM_H);
        int w = (int)__fdiv_rn((float)area, (float)h);
        w = min(max(w, 1), BM_W);
        int max_t = max(BM_H - h + 1, 1);
        int max_l = max(BM_W - w + 1, 1);
        s_top  = (int)__fmul_rn(rand_top[i],  (float)max_t);
        s_left = (int)__fmul_rn(rand_left[i], (float)max_l);
        s_h = h;
        s_w = w;
    }
    __syncthreads();

    const int top  = s_top, left = s_left, h = s_h, w = s_w;
    const int lane = tid & 31;
    const int warp = tid >> 5;

    float* ctx = out + (size_t)b * BM_SEQ;
    float* tgt = out + BM_HALF + (size_t)b * BM_SEQ;

    for (int r = warp; r < h; r += 4) {
        const int rowoff = (top + r) * BM_W + left;
        for (int c = lane; c < w; c += 32) {
            tgt[rowoff + c] = 1.0f;
            ctx[rowoff + c] = 0.0f;
        }
    }
}

extern "C" void kernel_launch(void* const* d_in, const int* in_sizes, int n_in,
                              void* d_out, int out_size)
{
    const float* scales_u  = (const float*)d_in[0];
    const float* rand_top  = (const float*)d_in[1];
    const float* rand_left = (const float*)d_in[2];
    float* out = (float*)d_out;

    fill_kernel<<<2048, 256>>>(out);
    raster_kernel<<<BM_BATCH * BM_NBLK, 128>>>(scales_u, rand_top, rand_left, out);
}

// round 12
// speedup vs baseline: 1.3732x; 1.3732x over previous
#include <cuda_runtime.h>
#include <cstdint>

// BlockMaskGenerator: 4 random rectangles per batch -> 256 x 16384 bool
// target mask + complement context mask (bool promoted to f32 by harness).
//   d_out = [context_mask (256*16384 f32), target_mask (256*16384 f32)]
// R10 postmortem: range32 missed the lower clamp -> negative hi/lo produced
// 0xFFFFFFFF words (rel_err 0.51). Fixed: clamp lo,hi into [0,32] first.
// Design per R9 finding: fill-shaped store kernel (2048 CTAs x 256 thr,
// 4 STG.128/thr, each warp-STG one contiguous 512B row) sustains ~8TB/s;
// values come from per-CTA precomputed 128-bit row masks in smem.

#define BM_BATCH   256
#define BM_NBLK    4
#define BM_H       128
#define BM_W       128
#define BM_SEQ     (BM_H * BM_W)
#define BM_HALF    (BM_BATCH * BM_SEQ)

// bits [lo,hi) of a 32-bit word, with lo,hi clamped into [0,32]
__device__ __forceinline__ unsigned range32(int lo, int hi)
{
    lo = min(max(lo, 0), 32);
    hi = min(max(hi, 0), 32);
    if (hi <= lo) return 0u;
    unsigned hm = (hi == 32) ? 0xFFFFFFFFu : ((1u << hi) - 1u);
    unsigned lm = (1u << lo) - 1u;   // lo in [0,31] here
    return hm & ~lm;
}

__global__ __launch_bounds__(256, 8)
void block_mask_kernel(const float* __restrict__ scales_u,
                       const float* __restrict__ rand_top,
                       const float* __restrict__ rand_left,
                       float* __restrict__ out)
{
    // Per-row 128-bit column membership masks (16 rows per CTA)
    __shared__ unsigned s_row[16][4];

    const int bid  = blockIdx.x;
    const int b    = bid >> 3;                 // batch (8 CTAs per batch)
    const int r0   = (bid & 7) * 16;           // first row this CTA owns
    const int tid  = threadIdx.x;
    const int lane = tid & 31;
    const int warp = tid >> 5;

    if (warp == 0) {
        // Lanes 0..3: rect chain (exact IEEE-rn sequence matching JAX)
        unsigned packed = 0u;
        if (lane < BM_NBLK) {
            const int i = b * BM_NBLK + lane;
            float scale = __fadd_rn(0.15f, __fmul_rn(scales_u[i], 0.05f));
            float areaf = __fmul_rn(__fmul_rn(scale, 128.0f), 128.0f); // pow2 exact
            int area = (int)areaf;                                     // trunc
            int h = (int)__fsqrt_rn(__fdiv_rn((float)area, 0.75f));
            h = min(max(h, 1), BM_H);
            int w = (int)__fdiv_rn((float)area, (float)h);
            w = min(max(w, 1), BM_W);
            int max_t = max(BM_H - h + 1, 1);
            int max_l = max(BM_W - w + 1, 1);
            int top  = (int)__fmul_rn(rand_top[i],  (float)max_t);
            int left = (int)__fmul_rn(rand_left[i], (float)max_l);
            packed = (unsigned)top | ((unsigned)(top + h) << 8)
                   | ((unsigned)left << 16) | ((unsigned)(left + w) << 24);
        }
        const unsigned p0 = __shfl_sync(0xFFFFFFFFu, packed, 0);
        const unsigned p1 = __shfl_sync(0xFFFFFFFFu, packed, 1);
        const unsigned p2 = __shfl_sync(0xFFFFFFFFu, packed, 2);
        const unsigned p3 = __shfl_sync(0xFFFFFFFFu, packed, 3);

        // Lanes 0..15: build this row's 128-bit column mask
        if (lane < 16) {
            const int row = r0 + lane;
            unsigned w0 = 0u, w1 = 0u, w2 = 0u, w3 = 0u;
            const unsigned pk[4] = {p0, p1, p2, p3};
#pragma unroll
            for (int j = 0; j < BM_NBLK; j++) {
                const unsigned p = pk[j];
                int tj = (int)(p & 0xFFu);
                int bj = (int)((p >> 8) & 0xFFu);
                if ((row >= tj) & (row < bj)) {
                    int lj = (int)((p >> 16) & 0xFFu);
                    int rj = (int)(p >> 24);
                    w0 |= range32(lj,      rj);
                    w1 |= range32(lj - 32, rj - 32);
                    w2 |= range32(lj - 64, rj - 64);
                    w3 |= range32(lj - 96, rj - 96);
                }
            }
            s_row[lane][0] = w0;
            s_row[lane][1] = w1;
            s_row[lane][2] = w2;
            s_row[lane][3] = w3;
        }
    }
    __syncthreads();

    // Main phase: warp w owns rows r0+2w, r0+2w+1; lane owns cols [4l,4l+4).
    // 4 STG.128 per thread, each warp-STG = one contiguous 512B row.
    const int ra = 2 * warp;
    const int rb = ra + 1;
    const int wi = lane >> 3;         // which 32-bit word of the row mask
    const int sh = (lane & 7) * 4;    // nibble shift within word

    const unsigned na = (s_row[ra][wi] >> sh) & 0xFu;
    const unsigned nb = (s_row[rb][wi] >> sh) & 0xFu;

    const unsigned ONE = 0x3F800000u;  // 1.0f
    uint4 ta, tb, ca, cb;
    ta.x = (na & 1u) ? ONE : 0u;  ca.x = ta.x ^ ONE;
    ta.y = (na & 2u) ? ONE : 0u;  ca.y = ta.y ^ ONE;
    ta.z = (na & 4u) ? ONE : 0u;  ca.z = ta.z ^ ONE;
    ta.w = (na & 8u) ? ONE : 0u;  ca.w = ta.w ^ ONE;
    tb.x = (nb & 1u) ? ONE : 0u;  cb.x = tb.x ^ ONE;
    tb.y = (nb & 2u) ? ONE : 0u;  cb.y = tb.y ^ ONE;
    tb.z = (nb & 4u) ? ONE : 0u;  cb.z = tb.z ^ ONE;
    tb.w = (nb & 8u) ? ONE : 0u;  cb.w = tb.w ^ ONE;

    float* ctx = out;
    float* tgt = out + BM_HALF;
    const size_t base = (size_t)b * BM_SEQ + (size_t)(r0 + ra) * BM_W + lane * 4;

    *reinterpret_cast<uint4*>(tgt + base)        = ta;
    *reinterpret_cast<uint4*>(tgt + base + BM_W) = tb;
    *reinterpret_cast<uint4*>(ctx + base)        = ca;
    *reinterpret_cast<uint4*>(ctx + base + BM_W) = cb;
}

extern "C" void kernel_launch(void* const* d_in, const int* in_sizes, int n_in,
                              void* d_out, int out_size)
{
    const float* scales_u  = (const float*)d_in[0];
    const float* rand_top  = (const float*)d_in[1];
    const float* rand_left = (const float*)d_in[2];
    float* out = (float*)d_out;

    block_mask_kernel<<<BM_BATCH * 8, 256>>>(scales_u, rand_top, rand_left, out);
}